// round 11
// baseline (speedup 1.0000x reference)
#include <cuda_runtime.h>

// GumbelTopK forward collapses to: per row, output 1.0 at positions of the
// top-64 values of (logits + gumbel_noise), ties broken by lowest index;
// 0.0 elsewhere. (cumsum(softmax) <= 64 mask is always all-ones; the
// straight-through trick makes the forward value exactly y_hard.)

#define N_COLS   8192
#define TOPK     64u
#define NTHREADS 256
#define VEC      8      // float4 chunks per thread: 8192/4/256 = 8
#define CAP      512    // candidate-list capacity for exact rank selection

__device__ __forceinline__ unsigned ordkey(float f) {
    // order-preserving map: larger float -> larger unsigned
    unsigned u = __float_as_uint(f);
    return (u & 0x80000000u) ? ~u : (u | 0x80000000u);
}

__global__ __launch_bounds__(NTHREADS) void gumbel_topk_kernel(
    const float* __restrict__ logits,
    const float* __restrict__ noise,
    float* __restrict__ out)
{
    __shared__ unsigned hist[256];
    __shared__ unsigned wsum[8];
    __shared__ unsigned s_selB, s_need, s_c, s_cnt;
    __shared__ unsigned listKey[CAP];
    __shared__ unsigned short listIdx[CAP];
    __shared__ unsigned char flag[N_COLS];

    const int t    = threadIdx.x;
    const int lane = t & 31;
    const int w    = t >> 5;
    const int row  = blockIdx.x;

    const float4* L = (const float4*)logits + (size_t)row * (N_COLS / 4);
    const float4* G = (const float4*)noise  + (size_t)row * (N_COLS / 4);

    // ---- load + key transform (keys stay in registers) ----
    unsigned key[VEC][4];
#pragma unroll
    for (int j = 0; j < VEC; j++) {
        float4 a = L[j * NTHREADS + t];
        float4 b = G[j * NTHREADS + t];
        key[j][0] = ordkey(a.x + b.x);
        key[j][1] = ordkey(a.y + b.y);
        key[j][2] = ordkey(a.z + b.z);
        key[j][3] = ordkey(a.w + b.w);
    }

    // ---- radix select: find prefix of the 64th-largest key ----
    unsigned prefix = 0, pmask = 0;
    unsigned need = TOPK;        // how many still needed within current prefix
    unsigned c = N_COLS;         // count of elements matching current prefix

    for (int bp = 3; bp >= 0; bp--) {
        hist[t] = 0;
        __syncthreads();
        const int shift = bp * 8;

        if (bp == 3) {
            // full participation: warp-aggregated atomics (values concentrate
            // in a few exponent buckets -> match_any collapses contention)
#pragma unroll
            for (int j = 0; j < VEC; j++)
#pragma unroll
                for (int k2 = 0; k2 < 4; k2++) {
                    unsigned b = key[j][k2] >> 24;
                    unsigned m = __match_any_sync(0xFFFFFFFFu, b);
                    if ((__ffs(m) - 1) == lane) atomicAdd(&hist[b], (unsigned)__popc(m));
                }
        } else {
#pragma unroll
            for (int j = 0; j < VEC; j++)
#pragma unroll
                for (int k2 = 0; k2 < 4; k2++) {
                    unsigned kk = key[j][k2];
                    if ((kk & pmask) == prefix)
                        atomicAdd(&hist[(kk >> shift) & 0xFFu], 1u);
                }
        }
        __syncthreads();

        // suffix scan over 256 bins: warp-level shfl scans + serial combine
        unsigned cbin = hist[t];
        unsigned s = cbin;
#pragma unroll
        for (int d = 1; d < 32; d <<= 1) {
            unsigned o = __shfl_down_sync(0xFFFFFFFFu, s, d);
            if (lane + d < 32) s += o;
        }
        if (lane == 0) wsum[w] = s;
        __syncthreads();
        if (t == 0) {
            unsigned tmp[8], run = 0;
            for (int i = 7; i >= 0; i--) { tmp[i] = run; run += wsum[i]; }
            for (int i = 0; i < 8; i++) wsum[i] = tmp[i];
        }
        __syncthreads();

        unsigned suff  = s + wsum[w];     // # matched elems with bin >= t
        unsigned above = suff - cbin;     // # matched elems with bin >  t
        if (suff >= need && above < need) {   // exactly one bin satisfies this
            s_selB = (unsigned)t;
            s_need = need - above;
            s_c    = cbin;
        }
        __syncthreads();
        unsigned b = s_selB;
        need  = s_need;
        c     = s_c;
        prefix |= b << shift;
        pmask  |= 0xFFu << shift;
        __syncthreads();   // protect hist/wsum/s_* reuse next iteration

        if (c <= CAP) break;   // few enough candidates for exact rank select
    }

    // ---- collect candidates (prefix-matching keys) ----
    if (t == 0) s_cnt = 0;
    __syncthreads();
#pragma unroll
    for (int j = 0; j < VEC; j++)
#pragma unroll
        for (int k2 = 0; k2 < 4; k2++) {
            unsigned kk = key[j][k2];
            if ((kk & pmask) == prefix) {
                unsigned slot = atomicAdd(&s_cnt, 1u);
                if (slot < CAP) {
                    listKey[slot] = kk;
                    listIdx[slot] = (unsigned short)((j * NTHREADS + t) * 4 + k2);
                }
            }
        }
    __syncthreads();
    unsigned cnt = min(s_cnt, (unsigned)CAP);

    // exact rank selection: (key desc, index asc) == lax.top_k tie-break
    for (unsigned s0 = t; s0 < cnt; s0 += NTHREADS) {
        unsigned k0 = listKey[s0];
        unsigned i0 = listIdx[s0];
        unsigned rank = 0;
        for (unsigned j2 = 0; j2 < cnt; j2++) {
            unsigned kj = listKey[j2];
            rank += (kj > k0) || (kj == k0 && listIdx[j2] < i0);
        }
        flag[i0] = (rank < need) ? (unsigned char)1 : (unsigned char)0;
    }
    __syncthreads();

    // ---- write output: 1.0 for selected, 0.0 otherwise ----
    float4* O = (float4*)out + (size_t)row * (N_COLS / 4);
#pragma unroll
    for (int j = 0; j < VEC; j++) {
        const int base = (j * NTHREADS + t) * 4;
        float4 v;
        {
            unsigned km = key[j][0] & pmask;
            v.x = (km > prefix) ? 1.0f : ((km == prefix && flag[base + 0]) ? 1.0f : 0.0f);
        }
        {
            unsigned km = key[j][1] & pmask;
            v.y = (km > prefix) ? 1.0f : ((km == prefix && flag[base + 1]) ? 1.0f : 0.0f);
        }
        {
            unsigned km = key[j][2] & pmask;
            v.z = (km > prefix) ? 1.0f : ((km == prefix && flag[base + 2]) ? 1.0f : 0.0f);
        }
        {
            unsigned km = key[j][3] & pmask;
            v.w = (km > prefix) ? 1.0f : ((km == prefix && flag[base + 3]) ? 1.0f : 0.0f);
        }
        O[j * NTHREADS + t] = v;
    }
}

extern "C" void kernel_launch(void* const* d_in, const int* in_sizes, int n_in,
                              void* d_out, int out_size)
{
    const float* logits = (const float*)d_in[0];
    const float* noise  = (const float*)d_in[1];
    float* out = (float*)d_out;
    int rows = in_sizes[0] / N_COLS;   // 2048
    gumbel_topk_kernel<<<rows, NTHREADS>>>(logits, noise, out);
}

// round 12
// speedup vs baseline: 1.0096x; 1.0096x over previous
#include <cuda_runtime.h>

// GumbelTopK forward collapses to: per row, output 1.0 at positions of the
// top-64 values of (logits + gumbel_noise), ties broken by lowest index;
// 0.0 elsewhere. (cumsum(softmax) <= 64 mask is always all-ones; the
// straight-through trick makes the forward value exactly y_hard.)

#define N_COLS   8192
#define TOPK     64u
#define NTHREADS 256
#define VEC      8      // float4 chunks per thread: 8192/4/256 = 8
#define CAP      512    // candidate-list capacity for exact rank selection

__device__ __forceinline__ unsigned ordkey(float f) {
    // order-preserving map: larger float -> larger unsigned
    unsigned u = __float_as_uint(f);
    return (u & 0x80000000u) ? ~u : (u | 0x80000000u);
}

__global__ __launch_bounds__(NTHREADS) void gumbel_topk_kernel(
    const float* __restrict__ logits,
    const float* __restrict__ noise,
    float* __restrict__ out)
{
    __shared__ unsigned hist[256];
    __shared__ unsigned wsum[8];
    __shared__ unsigned s_selB, s_need, s_c, s_cnt;
    __shared__ unsigned listKey[CAP];
    __shared__ unsigned short listIdx[CAP];
    __shared__ unsigned char flag[N_COLS];

    const int t    = threadIdx.x;
    const int lane = t & 31;
    const int w    = t >> 5;
    const int row  = blockIdx.x;

    const float4* L = (const float4*)logits + (size_t)row * (N_COLS / 4);
    const float4* G = (const float4*)noise  + (size_t)row * (N_COLS / 4);

    // ---- load + key transform (keys stay in registers) ----
    unsigned key[VEC][4];
#pragma unroll
    for (int j = 0; j < VEC; j++) {
        float4 a = L[j * NTHREADS + t];
        float4 b = G[j * NTHREADS + t];
        key[j][0] = ordkey(a.x + b.x);
        key[j][1] = ordkey(a.y + b.y);
        key[j][2] = ordkey(a.z + b.z);
        key[j][3] = ordkey(a.w + b.w);
    }

    // ---- radix select: find prefix of the 64th-largest key ----
    unsigned prefix = 0, pmask = 0;
    unsigned need = TOPK;        // how many still needed within current prefix
    unsigned c = N_COLS;         // count of elements matching current prefix

    for (int bp = 3; bp >= 0; bp--) {
        hist[t] = 0;
        __syncthreads();
        const int shift = bp * 8;

        if (bp == 3) {
            // full participation: warp-aggregated atomics (values concentrate
            // in a few exponent buckets -> match_any collapses contention)
#pragma unroll
            for (int j = 0; j < VEC; j++)
#pragma unroll
                for (int k2 = 0; k2 < 4; k2++) {
                    unsigned b = key[j][k2] >> 24;
                    unsigned m = __match_any_sync(0xFFFFFFFFu, b);
                    if ((__ffs(m) - 1) == lane) atomicAdd(&hist[b], (unsigned)__popc(m));
                }
        } else {
#pragma unroll
            for (int j = 0; j < VEC; j++)
#pragma unroll
                for (int k2 = 0; k2 < 4; k2++) {
                    unsigned kk = key[j][k2];
                    if ((kk & pmask) == prefix)
                        atomicAdd(&hist[(kk >> shift) & 0xFFu], 1u);
                }
        }
        __syncthreads();

        // suffix scan over 256 bins: warp-level shfl scans + serial combine
        unsigned cbin = hist[t];
        unsigned s = cbin;
#pragma unroll
        for (int d = 1; d < 32; d <<= 1) {
            unsigned o = __shfl_down_sync(0xFFFFFFFFu, s, d);
            if (lane + d < 32) s += o;
        }
        if (lane == 0) wsum[w] = s;
        __syncthreads();
        if (t == 0) {
            unsigned tmp[8], run = 0;
            for (int i = 7; i >= 0; i--) { tmp[i] = run; run += wsum[i]; }
            for (int i = 0; i < 8; i++) wsum[i] = tmp[i];
        }
        __syncthreads();

        unsigned suff  = s + wsum[w];     // # matched elems with bin >= t
        unsigned above = suff - cbin;     // # matched elems with bin >  t
        if (suff >= need && above < need) {   // exactly one bin satisfies this
            s_selB = (unsigned)t;
            s_need = need - above;
            s_c    = cbin;
        }
        __syncthreads();
        unsigned b = s_selB;
        need  = s_need;
        c     = s_c;
        prefix |= b << shift;
        pmask  |= 0xFFu << shift;
        __syncthreads();   // protect hist/wsum/s_* reuse next iteration

        if (c <= CAP) break;   // few enough candidates for exact rank select
    }

    // ---- collect candidates (prefix-matching keys) ----
    if (t == 0) s_cnt = 0;
    __syncthreads();
#pragma unroll
    for (int j = 0; j < VEC; j++)
#pragma unroll
        for (int k2 = 0; k2 < 4; k2++) {
            unsigned kk = key[j][k2];
            if ((kk & pmask) == prefix) {
                unsigned slot = atomicAdd(&s_cnt, 1u);
                if (slot < CAP) {
                    listKey[slot] = kk;
                    listIdx[slot] = (unsigned short)((j * NTHREADS + t) * 4 + k2);
                }
            }
        }
    __syncthreads();
    unsigned cnt = min(s_cnt, (unsigned)CAP);

    // exact rank selection: (key desc, index asc) == lax.top_k tie-break
    for (unsigned s0 = t; s0 < cnt; s0 += NTHREADS) {
        unsigned k0 = listKey[s0];
        unsigned i0 = listIdx[s0];
        unsigned rank = 0;
        for (unsigned j2 = 0; j2 < cnt; j2++) {
            unsigned kj = listKey[j2];
            rank += (kj > k0) || (kj == k0 && listIdx[j2] < i0);
        }
        flag[i0] = (rank < need) ? (unsigned char)1 : (unsigned char)0;
    }
    __syncthreads();

    // ---- write output: 1.0 for selected, 0.0 otherwise ----
    float4* O = (float4*)out + (size_t)row * (N_COLS / 4);
#pragma unroll
    for (int j = 0; j < VEC; j++) {
        const int base = (j * NTHREADS + t) * 4;
        float4 v;
        {
            unsigned km = key[j][0] & pmask;
            v.x = (km > prefix) ? 1.0f : ((km == prefix && flag[base + 0]) ? 1.0f : 0.0f);
        }
        {
            unsigned km = key[j][1] & pmask;
            v.y = (km > prefix) ? 1.0f : ((km == prefix && flag[base + 1]) ? 1.0f : 0.0f);
        }
        {
            unsigned km = key[j][2] & pmask;
            v.z = (km > prefix) ? 1.0f : ((km == prefix && flag[base + 2]) ? 1.0f : 0.0f);
        }
        {
            unsigned km = key[j][3] & pmask;
            v.w = (km > prefix) ? 1.0f : ((km == prefix && flag[base + 3]) ? 1.0f : 0.0f);
        }
        O[j * NTHREADS + t] = v;
    }
}

extern "C" void kernel_launch(void* const* d_in, const int* in_sizes, int n_in,
                              void* d_out, int out_size)
{
    const float* logits = (const float*)d_in[0];
    const float* noise  = (const float*)d_in[1];
    float* out = (float*)d_out;
    int rows = in_sizes[0] / N_COLS;   // 2048
    gumbel_topk_kernel<<<rows, NTHREADS>>>(logits, noise, out);
}